// round 8
// baseline (speedup 1.0000x reference)
#include <cuda_runtime.h>
#include <math.h>

#define Bz   64
#define Tt   128
#define TM1  127
#define Vv   10000
#define Ee   300
#define Hh   1024
#define G4   4096
#define MROWS (TM1*Bz)   // 8128
#define GRID_REC 128
#define CH    32         // kk per chunk
#define NCH   32         // chunks per K=1024
#define DEPTH 4          // cp.async ring depth

typedef unsigned long long ull;

// ---------------- scratch (device globals; no allocs allowed) ----------------
__device__ float g_xw[(size_t)MROWS * G4];     // precomputed x@w_ih0 + b0, (t,b,4H)
__device__ float g_h1all[(size_t)MROWS * Hh];  // all h1 states, (t,b,H)
__device__ float g_h0[2][Hh * Bz];             // ping-pong layer0 h state, K-MAJOR [k][b]
__device__ float g_h1[2][Hh * Bz];             // ping-pong layer1 h state, K-MAJOR [k][b]
__device__ float g_rowloss[MROWS];
__device__ unsigned g_barcnt;

// ---------------- f32x2 packed-FMA helpers (sm_100+) ----------------
__device__ __forceinline__ ull pk2(float x, float y) {
    ull r; asm("mov.b64 %0, {%1,%2};" : "=l"(r) : "f"(x), "f"(y)); return r;
}
__device__ __forceinline__ ull fma2(ull a, ull b, ull c) {
    ull d; asm("fma.rn.f32x2 %0, %1, %2, %3;" : "=l"(d) : "l"(a), "l"(b), "l"(c)); return d;
}
__device__ __forceinline__ float2 upk(ull v) {
    float2 f; asm("mov.b64 {%0,%1}, %2;" : "=f"(f.x), "=f"(f.y) : "l"(v)); return f;
}
__device__ __forceinline__ float sigf(float x) { return 1.0f / (1.0f + expf(-x)); }

__device__ __forceinline__ unsigned smem_u32(const void* p) {
    unsigned a;
    asm("{ .reg .u64 t; cvta.to.shared.u64 t, %1; cvt.u32.u64 %0, t; }" : "=r"(a) : "l"(p));
    return a;
}
__device__ __forceinline__ void cp16(unsigned dst, const void* src) {
    asm volatile("cp.async.cg.shared.global [%0], [%1], 16;" :: "r"(dst), "l"(src));
}

// grid-wide epoch barrier (all GRID_REC blocks co-resident: 128 <= #SMs)
__device__ __forceinline__ void gbar(unsigned target) {
    __syncthreads();
    if (threadIdx.x == 0) {
        __threadfence();
        atomicAdd(&g_barcnt, 1u);
        unsigned v;
        do {
            asm volatile("ld.acquire.gpu.u32 %0, [%1];" : "=r"(v) : "l"(&g_barcnt));
        } while (v < target);
    }
    __syncthreads();
}

// ---------------- init states ----------------
__global__ void k_init() {
    int i = blockIdx.x * blockDim.x + threadIdx.x;
    if (i < Bz * Hh) {
        g_h0[0][i] = 0.f; g_h1[0][i] = 0.f;
    }
    if (i == 0) g_barcnt = 0u;
}

// ---------------- K2: xW = gather(emb) @ w_ih0 + b0 ----------------
__global__ __launch_bounds__(256) void k_xw(const int* __restrict__ sent,
                                            const float* __restrict__ wordvec,
                                            const float* __restrict__ wih0,
                                            const float* __restrict__ b0) {
    __shared__ float As[8][128];
    __shared__ float Bs[8][128];
    __shared__ int stok[128];

    int tid = threadIdx.x;
    int n0 = blockIdx.x * 128;
    int m0 = blockIdx.y * 128;

    if (tid < 128) {
        int m = m0 + tid;
        int mc = (m < MROWS) ? m : (MROWS - 1);
        int t = mc >> 6, b = mc & 63;
        stok[tid] = sent[b * Tt + t];
    }
    __syncthreads();

    int tx = tid & 15, ty = tid >> 4;
    ull acc[8][4];
#pragma unroll
    for (int i = 0; i < 8; i++)
#pragma unroll
        for (int j = 0; j < 4; j++) acc[i][j] = 0ULL;

    for (int k0 = 0; k0 < Ee; k0 += 8) {
#pragma unroll
        for (int p = 0; p < 4; p++) {
            int idx = tid + p * 256;
            int r = idx & 127, kk = idx >> 7;
            int k = k0 + kk;
            As[kk][r] = (k < Ee) ? wordvec[(size_t)stok[r] * Ee + k] : 0.f;
            Bs[kk][r] = (k < Ee) ? wih0[(size_t)k * G4 + n0 + r] : 0.f;
        }
        __syncthreads();
#pragma unroll
        for (int kk = 0; kk < 8; kk++) {
            ull bf[4];
#pragma unroll
            for (int j = 0; j < 4; j++) bf[j] = *(const ull*)&Bs[kk][32 * j + 2 * tx];
#pragma unroll
            for (int i = 0; i < 8; i++) {
                float a = As[kk][ty + 16 * i];
                ull a2 = pk2(a, a);
#pragma unroll
                for (int j = 0; j < 4; j++) acc[i][j] = fma2(a2, bf[j], acc[i][j]);
            }
        }
        __syncthreads();
    }

#pragma unroll
    for (int i = 0; i < 8; i++) {
        int m = m0 + ty + 16 * i;
        if (m >= MROWS) continue;
        float* orow = g_xw + (size_t)m * G4 + n0;
#pragma unroll
        for (int j = 0; j < 4; j++) {
            float2 v = upk(acc[i][j]);
            int c = 32 * j + 2 * tx;
            orow[c]     = v.x + b0[n0 + c];
            orow[c + 1] = v.y + b0[n0 + c + 1];
        }
    }
}

// ---------------- K3: persistent recurrence, 3 groups, cp.async ring ----------
// Phase p: L0(t=p) and L1(t=p-1). Groups (256 thr each, full K=1024):
//   g0: h0[p-1] x whh0   g1: h0[p-1] x wih1   g2: h1[p-2] x whh1
// h state K-MAJOR in gmem -> contiguous chunk fills via cp.async (depth-4 ring,
// one named barrier per chunk). One __syncthreads + epilogues + gbar per phase.
#define SMEM_REC 152448
__global__ void __launch_bounds__(768) k_rec(const float* __restrict__ whh0,
                                             const float* __restrict__ wih1,
                                             const float* __restrict__ whh1,
                                             const float* __restrict__ b1) {
    extern __shared__ __align__(16) char smem[];
    float (*SH0)[CH][64]       = (float (*)[CH][64])(smem);                // 32768
    float (*SH1)[CH][64]       = (float (*)[CH][64])(smem + 32768);        // 32768
    float (*SW)[DEPTH][CH][32] = (float (*)[DEPTH][CH][32])(smem + 65536); // 49152
    float (*SGD)[64][33]       = (float (*)[64][33])(smem + 114688);       // 25344
    float (*SXW)[32]           = (float (*)[32])(smem + 140032);           // 8192
    float *SC0 = (float*)(smem + 148224);                                   // 2048
    float *SC1 = (float*)(smem + 150272);                                   // 2048
    float *SB1 = (float*)(smem + 152320);                                   // 128

    const int tid = threadIdx.x;
    const int g   = tid >> 8;            // group 0..2
    const int f   = tid & 255;
    const int tx  = f & 15, ty = f >> 4; // compute map: cols 2tx..+1, rows 4ty..+3
    const int j0  = blockIdx.x * 8;

    // w fill map (per group, one 16B cp.async per chunk)
    const int kkf = f >> 3;
    const int c4  = (f & 7) * 4;
    const int wcol4 = ((c4 >> 3) << 10) + j0 + (c4 & 7);
    const float* wsrc = (g == 0) ? whh0 : (g == 1) ? wih1 : whh1;

    // h0 fill map (tid<512: one 16B cp.async per chunk)
    const int h0k = tid >> 4, h0p = (tid & 15) * 4;
    // h1 fill map (g2: two 16B cp.async per chunk)
    const int h1k = f >> 3, h1p = (f & 7) * 8;

    if (tid < 512) { SC0[tid] = 0.f; SC1[tid] = 0.f; }
    if (tid < 32) SB1[tid] = b1[((tid >> 3) << 10) + j0 + (tid & 7)];
    __syncthreads();

    const unsigned sh0_base = smem_u32(&SH0[0][0][0]);
    const unsigned sh1_base = smem_u32(&SH1[0][0][0]);
    const unsigned sw_base  = smem_u32(&SW[0][0][0][0]);
    const unsigned sxw_base = smem_u32(&SXW[0][0]);

    unsigned tgt = 0;

    for (int p = 0; p < 128; p++) {
        const int cur = p & 1, nxt = cur ^ 1;
        const float* hsrc = (g == 2) ? g_h1[nxt] : g_h0[cur];   // K-major [k][64]

        auto issue_fill = [&](int c) {
            int buf = c & (DEPTH - 1);
            int kb = c * CH;
            if (g < 2) {
                cp16(sh0_base + (unsigned)((buf * CH + h0k) * 64 + h0p) * 4u,
                     hsrc + (size_t)(kb + h0k) * 64 + h0p);
            } else {
                const float* s = hsrc + (size_t)(kb + h1k) * 64 + h1p;
                unsigned d = sh1_base + (unsigned)((buf * CH + h1k) * 64 + h1p) * 4u;
                cp16(d, s);
                cp16(d + 16u, s + 4);
            }
            cp16(sw_base + (unsigned)(((g * DEPTH + buf) * CH + kkf) * 32 + c4) * 4u,
                 wsrc + (size_t)(kb + kkf) * G4 + wcol4);
            asm volatile("cp.async.commit_group;");
        };
        auto barg = [&]() {
            if (g < 2) asm volatile("bar.sync 1, 512;" ::: "memory");
            else       asm volatile("bar.sync 2, 256;" ::: "memory");
        };

        // xw[t=p] prefetch folded into chunk-0's commit group (tid<512)
        if (tid < 512 && p < 127) {
            int b = tid >> 3, q = tid & 7;
            const float* src = g_xw + ((size_t)p * Bz + b) * G4
                               + ((q >> 1) << 10) + j0 + (q & 1) * 4;
            cp16(sxw_base + (unsigned)(b * 32 + q * 4) * 4u, src);
        }
        issue_fill(0);
        issue_fill(1);
        issue_fill(2);

        ull a0 = 0, a1 = 0, a2 = 0, a3 = 0;

        for (int c = 0; c < NCH; c++) {
            if (c < NCH - 2)      asm volatile("cp.async.wait_group 2;");
            else if (c == NCH - 2) asm volatile("cp.async.wait_group 1;");
            else                   asm volatile("cp.async.wait_group 0;");
            barg();
            if (c + 3 < NCH) issue_fill(c + 3);

            int buf = c & (DEPTH - 1);
            const float* hb = (g < 2) ? &SH0[buf][0][0] : &SH1[buf][0][0];
            const float* wb = &SW[g][buf][0][0];
#pragma unroll
            for (int kk = 0; kk < CH; kk++) {
                ulonglong2 hA = *(const ulonglong2*)(hb + kk * 64 + 4 * ty);
                float2 w2     = *(const float2*)(wb + kk * 32 + 2 * tx);
                ull w0 = pk2(w2.x, w2.x);
                ull w1 = pk2(w2.y, w2.y);
                a0 = fma2(hA.x, w0, a0);
                a1 = fma2(hA.y, w0, a1);
                a2 = fma2(hA.x, w1, a2);
                a3 = fma2(hA.y, w1, a3);
            }
        }

        // stage gate partials
        {
            float2 v;
            v = upk(a0); SGD[g][4*ty+0][2*tx]   = v.x; SGD[g][4*ty+1][2*tx]   = v.y;
            v = upk(a1); SGD[g][4*ty+2][2*tx]   = v.x; SGD[g][4*ty+3][2*tx]   = v.y;
            v = upk(a2); SGD[g][4*ty+0][2*tx+1] = v.x; SGD[g][4*ty+1][2*tx+1] = v.y;
            v = upk(a3); SGD[g][4*ty+2][2*tx+1] = v.x; SGD[g][4*ty+3][2*tx+1] = v.y;
        }
        __syncthreads();

        if (g == 0) {
            if (p < 127) {
#pragma unroll
                for (int e = 0; e < 2; e++) {
                    int idx = f + 256 * e;
                    int bb = idx & 63, jj = idx >> 6;
                    float iv = SGD[0][bb][jj]      + SXW[bb][jj];
                    float fv = SGD[0][bb][8 + jj]  + SXW[bb][8 + jj];
                    float gv = SGD[0][bb][16 + jj] + SXW[bb][16 + jj];
                    float ov = SGD[0][bb][24 + jj] + SXW[bb][24 + jj];
                    float co = SC0[idx];
                    float cn = sigf(fv) * co + sigf(iv) * tanhf(gv);
                    float hn = sigf(ov) * tanhf(cn);
                    SC0[idx] = cn;
                    g_h0[nxt][(j0 + jj) * 64 + bb] = hn;    // K-major store
                }
            }
        } else if (g == 1) {
            if (p > 0) {
                int t = p - 1;
#pragma unroll
                for (int e = 0; e < 2; e++) {
                    int idx = f + 256 * e;
                    int bb = idx & 63, jj = idx >> 6;
                    float iv = SGD[1][bb][jj]      + SGD[2][bb][jj]      + SB1[jj];
                    float fv = SGD[1][bb][8 + jj]  + SGD[2][bb][8 + jj]  + SB1[8 + jj];
                    float gv = SGD[1][bb][16 + jj] + SGD[2][bb][16 + jj] + SB1[16 + jj];
                    float ov = SGD[1][bb][24 + jj] + SGD[2][bb][24 + jj] + SB1[24 + jj];
                    float co = SC1[idx];
                    float cn = sigf(fv) * co + sigf(iv) * tanhf(gv);
                    float hn = sigf(ov) * tanhf(cn);
                    SC1[idx] = cn;
                    g_h1[cur][(j0 + jj) * 64 + bb] = hn;    // K-major store
                    g_h1all[((size_t)t * Bz + bb) * Hh + j0 + jj] = hn;
                }
            }
        }

        if (p < 127) { tgt += GRID_REC; gbar(tgt); }
    }
}

// ---------------- K4: logits = h1_all @ w_out + b_out (double-buffered) -------
__global__ __launch_bounds__(256, 2) void k_logits(const float* __restrict__ wout,
                                                   const float* __restrict__ bout,
                                                   float* __restrict__ out) {
    __shared__ __align__(16) float As[2][8][132];
    __shared__ __align__(16) ull   Bd[2][8][128];
    __shared__ int aoff[128];

    int tid = threadIdx.x;
    int n0 = blockIdx.x * 128;
    int m0 = blockIdx.y * 128;

    if (tid < 128) {
        int m = m0 + tid;
        int mc = (m < MROWS) ? m : (MROWS - 1);
        int b = mc / 127, t = mc - b * 127;
        aoff[tid] = t * Bz + b;
    }
    __syncthreads();

    int tx = tid & 31, wy = tid >> 5;
    int ar = tid >> 1, akq = tid & 1;
    int bkk = tid >> 5, bc = (tid & 31) * 4;
    bool bok = (n0 + bc + 3 < Vv);

    ull acc[8][4];
#pragma unroll
    for (int p = 0; p < 8; p++)
#pragma unroll
        for (int j = 0; j < 4; j++) acc[p][j] = 0ULL;

    auto ldA = [&](int k0) -> float4 {
        return __ldg((const float4*)(g_h1all + (size_t)aoff[ar] * Hh + k0 + akq * 4));
    };
    auto ldB = [&](int k0) -> float4 {
        float4 bv = make_float4(0.f, 0.f, 0.f, 0.f);
        if (bok) {
            bv = __ldg((const float4*)(wout + (size_t)(k0 + bkk) * Vv + n0 + bc));
        } else {
            const float* wr = wout + (size_t)(k0 + bkk) * Vv;
            if (n0 + bc + 0 < Vv) bv.x = wr[n0 + bc + 0];
            if (n0 + bc + 1 < Vv) bv.y = wr[n0 + bc + 1];
            if (n0 + bc + 2 < Vv) bv.z = wr[n0 + bc + 2];
            if (n0 + bc + 3 < Vv) bv.w = wr[n0 + bc + 3];
        }
        return bv;
    };
    auto sts = [&](int bf, float4 av, float4 bv) {
        As[bf][akq * 4 + 0][ar] = av.x; As[bf][akq * 4 + 1][ar] = av.y;
        As[bf][akq * 4 + 2][ar] = av.z; As[bf][akq * 4 + 3][ar] = av.w;
        Bd[bf][bkk][bc + 0] = pk2(bv.x, bv.x); Bd[bf][bkk][bc + 1] = pk2(bv.y, bv.y);
        Bd[bf][bkk][bc + 2] = pk2(bv.z, bv.z); Bd[bf][bkk][bc + 3] = pk2(bv.w, bv.w);
    };

    float4 av = ldA(0), bv = ldB(0);
    sts(0, av, bv);
    __syncthreads();
    int buf = 0;

    for (int k0 = 0; k0 < Hh; k0 += 8) {
        bool more = (k0 + 8 < Hh);
        if (more) { av = ldA(k0 + 8); bv = ldB(k0 + 8); }
#pragma unroll
        for (int kk = 0; kk < 8; kk++) {
            ulonglong2 A0 = *(const ulonglong2*)&As[buf][kk][wy * 16 + 0];
            ulonglong2 A1 = *(const ulonglong2*)&As[buf][kk][wy * 16 + 4];
            ulonglong2 A2 = *(const ulonglong2*)&As[buf][kk][wy * 16 + 8];
            ulonglong2 A3 = *(const ulonglong2*)&As[buf][kk][wy * 16 + 12];
            ull hr[8] = {A0.x, A0.y, A1.x, A1.y, A2.x, A2.y, A3.x, A3.y};
#pragma unroll
            for (int j = 0; j < 4; j++) {
                ull w = Bd[buf][kk][tx + 32 * j];
#pragma unroll
                for (int p = 0; p < 8; p++) acc[p][j] = fma2(hr[p], w, acc[p][j]);
            }
        }
        if (more) sts(buf ^ 1, av, bv);
        __syncthreads();
        buf ^= 1;
    }

#pragma unroll
    for (int p = 0; p < 8; p++) {
        int m = m0 + wy * 16 + 2 * p;
#pragma unroll
        for (int j = 0; j < 4; j++) {
            int n = n0 + tx + 32 * j;
            if (n < Vv) {
                float2 v = upk(acc[p][j]);
                float bo = bout[n];
                if (m < MROWS)     out[1 + (size_t)m * Vv + n]       = v.x + bo;
                if (m + 1 < MROWS) out[1 + (size_t)(m + 1) * Vv + n] = v.y + bo;
            }
        }
    }
}

// ---------------- K5: per-row log-softmax at gt; masked by PAD ----------------
__global__ __launch_bounds__(256) void k_rowloss(const float* __restrict__ out,
                                                 const int* __restrict__ sent) {
    __shared__ float red[256];
    int m = blockIdx.x;
    const float* row = out + 1 + (size_t)m * Vv;
    int tid = threadIdx.x;

    float mx = -3.4e38f;
    for (int v = tid; v < Vv; v += 256) mx = fmaxf(mx, row[v]);
    red[tid] = mx; __syncthreads();
    for (int s = 128; s > 0; s >>= 1) {
        if (tid < s) red[tid] = fmaxf(red[tid], red[tid + s]);
        __syncthreads();
    }
    mx = red[0]; __syncthreads();

    float sm = 0.f;
    for (int v = tid; v < Vv; v += 256) sm += expf(row[v] - mx);
    red[tid] = sm; __syncthreads();
    for (int s = 128; s > 0; s >>= 1) {
        if (tid < s) red[tid] += red[tid + s];
        __syncthreads();
    }

    if (tid == 0) {
        int b = m / 127, t = m - b * 127;
        int gt = sent[b * Tt + t + 1];
        float lp = 0.f;
        if (gt != 0) lp = row[gt] - mx - logf(red[0]);
        g_rowloss[m] = lp;
    }
}

// ---------------- K6: deterministic loss reduction ----------------
__global__ void k_loss(const int* __restrict__ length, float* __restrict__ out) {
    __shared__ float sb[64];
    int b = threadIdx.x;
    float a = 0.f;
    for (int t = 0; t < TM1; t++) a += g_rowloss[b * TM1 + t];
    sb[b] = -a / (float)length[b];
    __syncthreads();
    if (b == 0) {
        float s = 0.f;
        for (int i = 0; i < 64; i++) s += sb[i];
        out[0] = s;
    }
}

// ---------------- host ----------------
extern "C" void kernel_launch(void* const* d_in, const int* in_sizes, int n_in,
                              void* d_out, int out_size) {
    const int*   sent    = (const int*)d_in[0];
    const int*   length  = (const int*)d_in[1];
    const float* wordvec = (const float*)d_in[2];
    const float* wih0    = (const float*)d_in[3];
    const float* whh0    = (const float*)d_in[4];
    const float* b0      = (const float*)d_in[5];
    const float* wih1    = (const float*)d_in[6];
    const float* whh1    = (const float*)d_in[7];
    const float* b1      = (const float*)d_in[8];
    const float* wout    = (const float*)d_in[9];
    const float* bout    = (const float*)d_in[10];
    float* out = (float*)d_out;

    static int smem_set = 0;
    if (!smem_set) {
        cudaFuncSetAttribute(k_rec, cudaFuncAttributeMaxDynamicSharedMemorySize, SMEM_REC);
        smem_set = 1;
    }

    k_init<<<256, 256>>>();
    k_xw<<<dim3(G4 / 128, 64), 256>>>(sent, wordvec, wih0, b0);
    k_rec<<<GRID_REC, 768, SMEM_REC>>>(whh0, wih1, whh1, b1);
    k_logits<<<dim3((Vv + 127) / 128, (MROWS + 127) / 128), 256>>>(wout, bout, out);
    k_rowloss<<<MROWS, 256>>>(out, sent);
    k_loss<<<1, 64>>>(length, out);
}

// round 9
// speedup vs baseline: 1.1642x; 1.1642x over previous
#include <cuda_runtime.h>
#include <math.h>

#define Bz   64
#define Tt   128
#define TM1  127
#define Vv   10000
#define Ee   300
#define Hh   1024
#define G4   4096
#define MROWS (TM1*Bz)   // 8128
#define GRID_REC 256     // 2 blocks per SM
#define CH    32
#define NCH   32

typedef unsigned long long ull;

// ---------------- scratch (device globals; no allocs allowed) ----------------
__device__ float g_xw[(size_t)MROWS * G4];     // x@w_ih0 + b0, (t,b,4H)
__device__ float g_h1all[(size_t)MROWS * Hh];  // all h1 states, (t,b,H)
__device__ float g_h0[2][Hh * Bz];             // layer0 h, K-MAJOR [k][b]
__device__ float g_h1[2][Hh * Bz];             // layer1 h, K-MAJOR [k][b]
__device__ float g_rowloss[MROWS];
__device__ unsigned g_barcnt;

// ---------------- f32x2 packed-FMA helpers (sm_100+) ----------------
__device__ __forceinline__ ull pk2(float x, float y) {
    ull r; asm("mov.b64 %0, {%1,%2};" : "=l"(r) : "f"(x), "f"(y)); return r;
}
__device__ __forceinline__ ull fma2(ull a, ull b, ull c) {
    ull d; asm("fma.rn.f32x2 %0, %1, %2, %3;" : "=l"(d) : "l"(a), "l"(b), "l"(c)); return d;
}
__device__ __forceinline__ float2 upk(ull v) {
    float2 f; asm("mov.b64 {%0,%1}, %2;" : "=f"(f.x), "=f"(f.y) : "l"(v)); return f;
}
__device__ __forceinline__ float sigf(float x) { return 1.0f / (1.0f + expf(-x)); }

__device__ __forceinline__ unsigned smem_u32(const void* p) {
    unsigned a;
    asm("{ .reg .u64 t; cvta.to.shared.u64 t, %1; cvt.u32.u64 %0, t; }" : "=r"(a) : "l"(p));
    return a;
}
__device__ __forceinline__ void cp16(unsigned dst, const void* src) {
    asm volatile("cp.async.cg.shared.global [%0], [%1], 16;" :: "r"(dst), "l"(src));
}

// grid-wide epoch barrier (all GRID_REC blocks co-resident: 256 <= 2*#SMs)
__device__ __forceinline__ void gbar(unsigned target) {
    __syncthreads();
    if (threadIdx.x == 0) {
        __threadfence();
        atomicAdd(&g_barcnt, 1u);
        unsigned v;
        do {
            asm volatile("ld.acquire.gpu.u32 %0, [%1];" : "=r"(v) : "l"(&g_barcnt));
        } while (v < target);
    }
    __syncthreads();
}

// ---------------- init states ----------------
__global__ void k_init() {
    int i = blockIdx.x * blockDim.x + threadIdx.x;
    if (i < Bz * Hh) {
        g_h0[0][i] = 0.f; g_h1[0][i] = 0.f;
    }
    if (i == 0) g_barcnt = 0u;
}

// ---------------- K2: xW = gather(emb) @ w_ih0 + b0 ----------------
__global__ __launch_bounds__(256) void k_xw(const int* __restrict__ sent,
                                            const float* __restrict__ wordvec,
                                            const float* __restrict__ wih0,
                                            const float* __restrict__ b0) {
    __shared__ float As[8][128];
    __shared__ float Bs[8][128];
    __shared__ int stok[128];

    int tid = threadIdx.x;
    int n0 = blockIdx.x * 128;
    int m0 = blockIdx.y * 128;

    if (tid < 128) {
        int m = m0 + tid;
        int mc = (m < MROWS) ? m : (MROWS - 1);
        int t = mc >> 6, b = mc & 63;
        stok[tid] = sent[b * Tt + t];
    }
    __syncthreads();

    int tx = tid & 15, ty = tid >> 4;
    ull acc[8][4];
#pragma unroll
    for (int i = 0; i < 8; i++)
#pragma unroll
        for (int j = 0; j < 4; j++) acc[i][j] = 0ULL;

    for (int k0 = 0; k0 < Ee; k0 += 8) {
#pragma unroll
        for (int p = 0; p < 4; p++) {
            int idx = tid + p * 256;
            int r = idx & 127, kk = idx >> 7;
            int k = k0 + kk;
            As[kk][r] = (k < Ee) ? wordvec[(size_t)stok[r] * Ee + k] : 0.f;
            Bs[kk][r] = (k < Ee) ? wih0[(size_t)k * G4 + n0 + r] : 0.f;
        }
        __syncthreads();
#pragma unroll
        for (int kk = 0; kk < 8; kk++) {
            ull bf[4];
#pragma unroll
            for (int j = 0; j < 4; j++) bf[j] = *(const ull*)&Bs[kk][32 * j + 2 * tx];
#pragma unroll
            for (int i = 0; i < 8; i++) {
                float a = As[kk][ty + 16 * i];
                ull a2 = pk2(a, a);
#pragma unroll
                for (int j = 0; j < 4; j++) acc[i][j] = fma2(a2, bf[j], acc[i][j]);
            }
        }
        __syncthreads();
    }

#pragma unroll
    for (int i = 0; i < 8; i++) {
        int m = m0 + ty + 16 * i;
        if (m >= MROWS) continue;
        float* orow = g_xw + (size_t)m * G4 + n0;
#pragma unroll
        for (int j = 0; j < 4; j++) {
            float2 v = upk(acc[i][j]);
            int c = 32 * j + 2 * tx;
            orow[c]     = v.x + b0[n0 + c];
            orow[c + 1] = v.y + b0[n0 + c + 1];
        }
    }
}

// ---------------- K3: persistent recurrence, 256 blocks (2/SM) ----------------
// Phase p: L0(t=p) and L1(t=p-1). Block owns 4 hidden units (16 gate cols).
// 3 groups x 128 thr, each a full-K GEMM:
//   g0: h0[p-1] x whh0   g1: h0[p-1] x wih1   g2: h1[p-2] x whh1
// Register-prefetch double buffer (LDG before compute, STS after), h K-major.
#define SMEM_REC 67392
__global__ void __launch_bounds__(384, 2) k_rec(const float* __restrict__ whh0,
                                                const float* __restrict__ wih1,
                                                const float* __restrict__ whh1,
                                                const float* __restrict__ b1) {
    extern __shared__ __align__(16) char smem[];
    float (*SH0)[CH][64]    = (float (*)[CH][64])(smem);              // 16384
    float (*SH1)[CH][64]    = (float (*)[CH][64])(smem + 16384);      // 16384
    float (*SW)[2][CH][20]  = (float (*)[2][CH][20])(smem + 32768);   // 15360
    float (*SGD)[64][17]    = (float (*)[64][17])(smem + 48128);      // 13056
    float (*SXW)[16]        = (float (*)[16])(smem + 61184);          // 4096
    float *SC0 = (float*)(smem + 65280);                               // 1024
    float *SC1 = (float*)(smem + 66304);                               // 1024
    float *SB1 = (float*)(smem + 67328);                               // 64

    const int tid = threadIdx.x;
    const int g   = tid >> 7;            // group 0..2
    const int f   = tid & 127;
    const int tx  = f & 7, ty = f >> 3;  // compute: cols 2tx..+1 (16), rows 4ty..+3 (64)
    const int j0  = blockIdx.x * 4;

    // w fill: 128 thr x 1 float4 = 32kk x 16cols
    const int kkf = f >> 2, cq = f & 3;
    const float* wsrc = (g == 0) ? whh0 : (g == 1) ? wih1 : whh1;
    const size_t wofs = (size_t)cq * Hh + j0;
    // h0 fill (tid<256): 2 float4 each
    const int h0k = tid >> 3, h0p = (tid & 7) * 8;
    // h1 fill (g2): 4 float4 each
    const int h1k = f >> 2, h1p = (f & 3) * 16;

    if (tid < 256) { SC0[tid] = 0.f; SC1[tid] = 0.f; }
    if (tid < 16) SB1[tid] = b1[(tid >> 2) * Hh + j0 + (tid & 3)];
    __syncthreads();

    const unsigned sxw_base = smem_u32(&SXW[0][0]);

    float4 r0, r1, r2, r3, pw;

    unsigned tgt = 0;

    for (int p = 0; p < 128; p++) {
        const int cur = p & 1, nxt = cur ^ 1;
        const float* hsrc = (g == 2) ? g_h1[nxt] : g_h0[cur];   // K-major [k][64]

        auto ld_fill = [&](int kb) {
            if (tid < 256) {
                r0 = __ldcg((const float4*)(hsrc + (size_t)(kb + h0k) * 64 + h0p));
                r1 = __ldcg((const float4*)(hsrc + (size_t)(kb + h0k) * 64 + h0p + 4));
            } else {
                const float* s = hsrc + (size_t)(kb + h1k) * 64 + h1p;
                r0 = __ldcg((const float4*)(s));
                r1 = __ldcg((const float4*)(s + 4));
                r2 = __ldcg((const float4*)(s + 8));
                r3 = __ldcg((const float4*)(s + 12));
            }
            pw = __ldg((const float4*)(wsrc + (size_t)(kb + kkf) * G4 + wofs));
        };
        auto st_fill = [&](int buf) {
            if (tid < 256) {
                *(float4*)&SH0[buf][h0k][h0p]     = r0;
                *(float4*)&SH0[buf][h0k][h0p + 4] = r1;
            } else {
                *(float4*)&SH1[buf][h1k][h1p]      = r0;
                *(float4*)&SH1[buf][h1k][h1p + 4]  = r1;
                *(float4*)&SH1[buf][h1k][h1p + 8]  = r2;
                *(float4*)&SH1[buf][h1k][h1p + 12] = r3;
            }
            *(float4*)&SW[g][buf][kkf][cq * 4] = pw;
        };
        auto barg = [&]() {
            if (g < 2) asm volatile("bar.sync 1, 256;" ::: "memory");
            else       asm volatile("bar.sync 2, 128;" ::: "memory");
        };

        // xw[t=p] prefetch (64 x 16) via cp.async, tid<256
        if (tid < 256 && p < 127) {
            int b = tid >> 2, q = tid & 3;
            const float* src = g_xw + ((size_t)p * Bz + b) * G4 + (size_t)q * Hh + j0;
            cp16(sxw_base + (unsigned)(b * 16 + q * 4) * 4u, src);
            asm volatile("cp.async.commit_group;");
        }

        ull a0 = 0, a1 = 0, a2 = 0, a3 = 0;

        ld_fill(0);
        st_fill(0);
        barg();

        int buf = 0;
        for (int c = 0; c < NCH; c++) {
            if (c < NCH - 1) ld_fill((c + 1) * CH);
            {
                const float* hb = (g < 2) ? &SH0[buf][0][0] : &SH1[buf][0][0];
                const float* wb = &SW[g][buf][0][0];
#pragma unroll
                for (int kk = 0; kk < CH; kk++) {
                    ulonglong2 hA = *(const ulonglong2*)(hb + kk * 64 + 4 * ty);
                    float2 w2     = *(const float2*)(wb + kk * 20 + 2 * tx);
                    ull w0 = pk2(w2.x, w2.x);
                    ull w1 = pk2(w2.y, w2.y);
                    a0 = fma2(hA.x, w0, a0);
                    a1 = fma2(hA.y, w0, a1);
                    a2 = fma2(hA.x, w1, a2);
                    a3 = fma2(hA.y, w1, a3);
                }
            }
            if (c < NCH - 1) st_fill(buf ^ 1);
            barg();
            buf ^= 1;
        }

        // stage gate partials
        {
            float2 v;
            v = upk(a0); SGD[g][4*ty+0][2*tx]   = v.x; SGD[g][4*ty+1][2*tx]   = v.y;
            v = upk(a1); SGD[g][4*ty+2][2*tx]   = v.x; SGD[g][4*ty+3][2*tx]   = v.y;
            v = upk(a2); SGD[g][4*ty+0][2*tx+1] = v.x; SGD[g][4*ty+1][2*tx+1] = v.y;
            v = upk(a3); SGD[g][4*ty+2][2*tx+1] = v.x; SGD[g][4*ty+3][2*tx+1] = v.y;
        }
        if (tid < 256 && p < 127) asm volatile("cp.async.wait_group 0;");
        __syncthreads();

        if (g == 0) {
            if (p < 127) {
#pragma unroll
                for (int e = 0; e < 2; e++) {
                    int idx = f + 128 * e;          // 0..255
                    int bb = idx & 63, jj = idx >> 6;  // jj 0..3
                    float iv = SGD[0][bb][jj]      + SXW[bb][jj];
                    float fv = SGD[0][bb][4 + jj]  + SXW[bb][4 + jj];
                    float gv = SGD[0][bb][8 + jj]  + SXW[bb][8 + jj];
                    float ov = SGD[0][bb][12 + jj] + SXW[bb][12 + jj];
                    float co = SC0[idx];
                    float cn = sigf(fv) * co + sigf(iv) * tanhf(gv);
                    float hn = sigf(ov) * tanhf(cn);
                    SC0[idx] = cn;
                    g_h0[nxt][(size_t)(j0 + jj) * 64 + bb] = hn;
                }
            }
        } else if (g == 1) {
            if (p > 0) {
                int t = p - 1;
#pragma unroll
                for (int e = 0; e < 2; e++) {
                    int idx = f + 128 * e;
                    int bb = idx & 63, jj = idx >> 6;
                    float iv = SGD[1][bb][jj]      + SGD[2][bb][jj]      + SB1[jj];
                    float fv = SGD[1][bb][4 + jj]  + SGD[2][bb][4 + jj]  + SB1[4 + jj];
                    float gv = SGD[1][bb][8 + jj]  + SGD[2][bb][8 + jj]  + SB1[8 + jj];
                    float ov = SGD[1][bb][12 + jj] + SGD[2][bb][12 + jj] + SB1[12 + jj];
                    float co = SC1[idx];
                    float cn = sigf(fv) * co + sigf(iv) * tanhf(gv);
                    float hn = sigf(ov) * tanhf(cn);
                    SC1[idx] = cn;
                    g_h1[cur][(size_t)(j0 + jj) * 64 + bb] = hn;
                    g_h1all[((size_t)t * Bz + bb) * Hh + j0 + jj] = hn;
                }
            }
        }

        if (p < 127) { tgt += GRID_REC; gbar(tgt); }
    }
}

// ---------------- K4: logits = h1_all @ w_out + b_out (double-buffered) -------
__global__ __launch_bounds__(256, 2) void k_logits(const float* __restrict__ wout,
                                                   const float* __restrict__ bout,
                                                   float* __restrict__ out) {
    __shared__ __align__(16) float As[2][8][132];
    __shared__ __align__(16) ull   Bd[2][8][128];
    __shared__ int aoff[128];

    int tid = threadIdx.x;
    int n0 = blockIdx.x * 128;
    int m0 = blockIdx.y * 128;

    if (tid < 128) {
        int m = m0 + tid;
        int mc = (m < MROWS) ? m : (MROWS - 1);
        int b = mc / 127, t = mc - b * 127;
        aoff[tid] = t * Bz + b;
    }
    __syncthreads();

    int tx = tid & 31, wy = tid >> 5;
    int ar = tid >> 1, akq = tid & 1;
    int bkk = tid >> 5, bc = (tid & 31) * 4;
    bool bok = (n0 + bc + 3 < Vv);

    ull acc[8][4];
#pragma unroll
    for (int p = 0; p < 8; p++)
#pragma unroll
        for (int j = 0; j < 4; j++) acc[p][j] = 0ULL;

    auto ldA = [&](int k0) -> float4 {
        return __ldg((const float4*)(g_h1all + (size_t)aoff[ar] * Hh + k0 + akq * 4));
    };
    auto ldB = [&](int k0) -> float4 {
        float4 bv = make_float4(0.f, 0.f, 0.f, 0.f);
        if (bok) {
            bv = __ldg((const float4*)(wout + (size_t)(k0 + bkk) * Vv + n0 + bc));
        } else {
            const float* wr = wout + (size_t)(k0 + bkk) * Vv;
            if (n0 + bc + 0 < Vv) bv.x = wr[n0 + bc + 0];
            if (n0 + bc + 1 < Vv) bv.y = wr[n0 + bc + 1];
            if (n0 + bc + 2 < Vv) bv.z = wr[n0 + bc + 2];
            if (n0 + bc + 3 < Vv) bv.w = wr[n0 + bc + 3];
        }
        return bv;
    };
    auto sts = [&](int bf, float4 av, float4 bv) {
        As[bf][akq * 4 + 0][ar] = av.x; As[bf][akq * 4 + 1][ar] = av.y;
        As[bf][akq * 4 + 2][ar] = av.z; As[bf][akq * 4 + 3][ar] = av.w;
        Bd[bf][bkk][bc + 0] = pk2(bv.x, bv.x); Bd[bf][bkk][bc + 1] = pk2(bv.y, bv.y);
        Bd[bf][bkk][bc + 2] = pk2(bv.z, bv.z); Bd[bf][bkk][bc + 3] = pk2(bv.w, bv.w);
    };

    float4 av = ldA(0), bv = ldB(0);
    sts(0, av, bv);
    __syncthreads();
    int buf = 0;

    for (int k0 = 0; k0 < Hh; k0 += 8) {
        bool more = (k0 + 8 < Hh);
        if (more) { av = ldA(k0 + 8); bv = ldB(k0 + 8); }
#pragma unroll
        for (int kk = 0; kk < 8; kk++) {
            ulonglong2 A0 = *(const ulonglong2*)&As[buf][kk][wy * 16 + 0];
            ulonglong2 A1 = *(const ulonglong2*)&As[buf][kk][wy * 16 + 4];
            ulonglong2 A2 = *(const ulonglong2*)&As[buf][kk][wy * 16 + 8];
            ulonglong2 A3 = *(const ulonglong2*)&As[buf][kk][wy * 16 + 12];
            ull hr[8] = {A0.x, A0.y, A1.x, A1.y, A2.x, A2.y, A3.x, A3.y};
#pragma unroll
            for (int j = 0; j < 4; j++) {
                ull w = Bd[buf][kk][tx + 32 * j];
#pragma unroll
                for (int p = 0; p < 8; p++) acc[p][j] = fma2(hr[p], w, acc[p][j]);
            }
        }
        if (more) sts(buf ^ 1, av, bv);
        __syncthreads();
        buf ^= 1;
    }

#pragma unroll
    for (int p = 0; p < 8; p++) {
        int m = m0 + wy * 16 + 2 * p;
#pragma unroll
        for (int j = 0; j < 4; j++) {
            int n = n0 + tx + 32 * j;
            if (n < Vv) {
                float2 v = upk(acc[p][j]);
                float bo = bout[n];
                if (m < MROWS)     out[1 + (size_t)m * Vv + n]       = v.x + bo;
                if (m + 1 < MROWS) out[1 + (size_t)(m + 1) * Vv + n] = v.y + bo;
            }
        }
    }
}

// ---------------- K5: per-row log-softmax at gt; masked by PAD ----------------
__global__ __launch_bounds__(256) void k_rowloss(const float* __restrict__ out,
                                                 const int* __restrict__ sent) {
    __shared__ float red[256];
    int m = blockIdx.x;
    const float* row = out + 1 + (size_t)m * Vv;
    int tid = threadIdx.x;

    float mx = -3.4e38f;
    for (int v = tid; v < Vv; v += 256) mx = fmaxf(mx, row[v]);
    red[tid] = mx; __syncthreads();
    for (int s = 128; s > 0; s >>= 1) {
        if (tid < s) red[tid] = fmaxf(red[tid], red[tid + s]);
        __syncthreads();
    }
    mx = red[0]; __syncthreads();

    float sm = 0.f;
    for (int v = tid; v < Vv; v += 256) sm += expf(row[v] - mx);
    red[tid] = sm; __syncthreads();
    for (int s = 128; s > 0; s >>= 1) {
        if (tid < s) red[tid] += red[tid + s];
        __syncthreads();
    }

    if (tid == 0) {
        int b = m / 127, t = m - b * 127;
        int gt = sent[b * Tt + t + 1];
        float lp = 0.f;
        if (gt != 0) lp = row[gt] - mx - logf(red[0]);
        g_rowloss[m] = lp;
    }
}

// ---------------- K6: deterministic loss reduction ----------------
__global__ void k_loss(const int* __restrict__ length, float* __restrict__ out) {
    __shared__ float sb[64];
    int b = threadIdx.x;
    float a = 0.f;
    for (int t = 0; t < TM1; t++) a += g_rowloss[b * TM1 + t];
    sb[b] = -a / (float)length[b];
    __syncthreads();
    if (b == 0) {
        float s = 0.f;
        for (int i = 0; i < 64; i++) s += sb[i];
        out[0] = s;
    }
}

// ---------------- host ----------------
extern "C" void kernel_launch(void* const* d_in, const int* in_sizes, int n_in,
                              void* d_out, int out_size) {
    const int*   sent    = (const int*)d_in[0];
    const int*   length  = (const int*)d_in[1];
    const float* wordvec = (const float*)d_in[2];
    const float* wih0    = (const float*)d_in[3];
    const float* whh0    = (const float*)d_in[4];
    const float* b0      = (const float*)d_in[5];
    const float* wih1    = (const float*)d_in[6];
    const float* whh1    = (const float*)d_in[7];
    const float* b1      = (const float*)d_in[8];
    const float* wout    = (const float*)d_in[9];
    const float* bout    = (const float*)d_in[10];
    float* out = (float*)d_out;

    static int smem_set = 0;
    if (!smem_set) {
        cudaFuncSetAttribute(k_rec, cudaFuncAttributeMaxDynamicSharedMemorySize, SMEM_REC);
        smem_set = 1;
    }

    k_init<<<256, 256>>>();
    k_xw<<<dim3(G4 / 128, 64), 256>>>(sent, wordvec, wih0, b0);
    k_rec<<<GRID_REC, 384, SMEM_REC>>>(whh0, wih1, whh1, b1);
    k_logits<<<dim3((Vv + 127) / 128, (MROWS + 127) / 128), 256>>>(wout, bout, out);
    k_rowloss<<<MROWS, 256>>>(out, sent);
    k_loss<<<1, 64>>>(length, out);
}

// round 11
// speedup vs baseline: 1.4874x; 1.2776x over previous
#include <cuda_runtime.h>
#include <math.h>

#define Bz   64
#define Tt   128
#define TM1  127
#define Vv   10000
#define Ee   300
#define Hh   1024
#define G4   4096
#define MROWS (TM1*Bz)   // 8128
#define GRID_REC 128
#define CH    32
#define NCH   32

typedef unsigned long long ull;

// ---------------- scratch (device globals; no allocs allowed) ----------------
__device__ float g_xw[(size_t)MROWS * G4];     // x@w_ih0 + b0, (t,b,4H)
__device__ float g_h1all[(size_t)MROWS * Hh];  // all h1 states, (t,b,H)
__device__ float g_h0[2][Hh * Bz];             // layer0 h, K-MAJOR [k][b]
__device__ float g_h1[2][Hh * Bz];             // layer1 h, K-MAJOR [k][b]
__device__ float g_rowloss[MROWS];
__device__ unsigned g_barcnt;

// ---------------- f32x2 packed-FMA helpers (sm_100+) ----------------
__device__ __forceinline__ ull pk2(float x, float y) {
    ull r; asm("mov.b64 %0, {%1,%2};" : "=l"(r) : "f"(x), "f"(y)); return r;
}
__device__ __forceinline__ ull fma2(ull a, ull b, ull c) {
    ull d; asm("fma.rn.f32x2 %0, %1, %2, %3;" : "=l"(d) : "l"(a), "l"(b), "l"(c)); return d;
}
__device__ __forceinline__ float2 upk(ull v) {
    float2 f; asm("mov.b64 {%0,%1}, %2;" : "=f"(f.x), "=f"(f.y) : "l"(v)); return f;
}
__device__ __forceinline__ float sigf(float x) { return 1.0f / (1.0f + expf(-x)); }

__device__ __forceinline__ unsigned smem_u32(const void* p) {
    unsigned a;
    asm("{ .reg .u64 t; cvta.to.shared.u64 t, %1; cvt.u32.u64 %0, t; }" : "=r"(a) : "l"(p));
    return a;
}
__device__ __forceinline__ void cp16(unsigned dst, const void* src) {
    asm volatile("cp.async.cg.shared.global [%0], [%1], 16;" :: "r"(dst), "l"(src));
}

// grid-wide epoch barrier (all GRID_REC blocks co-resident: 128 <= #SMs)
__device__ __forceinline__ void gbar(unsigned target) {
    __syncthreads();
    if (threadIdx.x == 0) {
        __threadfence();
        atomicAdd(&g_barcnt, 1u);
        unsigned v;
        do {
            asm volatile("ld.acquire.gpu.u32 %0, [%1];" : "=r"(v) : "l"(&g_barcnt));
        } while (v < target);
    }
    __syncthreads();
}

// ---------------- init states ----------------
__global__ void k_init() {
    int i = blockIdx.x * blockDim.x + threadIdx.x;
    if (i < Bz * Hh) {
        g_h0[0][i] = 0.f; g_h1[0][i] = 0.f;
    }
    if (i == 0) g_barcnt = 0u;
}

// ---------------- K2: xW = gather(emb) @ w_ih0 + b0 ----------------
__global__ __launch_bounds__(256) void k_xw(const int* __restrict__ sent,
                                            const float* __restrict__ wordvec,
                                            const float* __restrict__ wih0,
                                            const float* __restrict__ b0) {
    __shared__ float As[8][128];
    __shared__ float Bs[8][128];
    __shared__ int stok[128];

    int tid = threadIdx.x;
    int n0 = blockIdx.x * 128;
    int m0 = blockIdx.y * 128;

    if (tid < 128) {
        int m = m0 + tid;
        int mc = (m < MROWS) ? m : (MROWS - 1);
        int t = mc >> 6, b = mc & 63;
        stok[tid] = sent[b * Tt + t];
    }
    __syncthreads();

    int tx = tid & 15, ty = tid >> 4;
    ull acc[8][4];
#pragma unroll
    for (int i = 0; i < 8; i++)
#pragma unroll
        for (int j = 0; j < 4; j++) acc[i][j] = 0ULL;

    for (int k0 = 0; k0 < Ee; k0 += 8) {
#pragma unroll
        for (int p = 0; p < 4; p++) {
            int idx = tid + p * 256;
            int r = idx & 127, kk = idx >> 7;
            int k = k0 + kk;
            As[kk][r] = (k < Ee) ? wordvec[(size_t)stok[r] * Ee + k] : 0.f;
            Bs[kk][r] = (k < Ee) ? wih0[(size_t)k * G4 + n0 + r] : 0.f;
        }
        __syncthreads();
#pragma unroll
        for (int kk = 0; kk < 8; kk++) {
            ull bf[4];
#pragma unroll
            for (int j = 0; j < 4; j++) bf[j] = *(const ull*)&Bs[kk][32 * j + 2 * tx];
#pragma unroll
            for (int i = 0; i < 8; i++) {
                float a = As[kk][ty + 16 * i];
                ull a2 = pk2(a, a);
#pragma unroll
                for (int j = 0; j < 4; j++) acc[i][j] = fma2(a2, bf[j], acc[i][j]);
            }
        }
        __syncthreads();
    }

#pragma unroll
    for (int i = 0; i < 8; i++) {
        int m = m0 + ty + 16 * i;
        if (m >= MROWS) continue;
        float* orow = g_xw + (size_t)m * G4 + n0;
#pragma unroll
        for (int j = 0; j < 4; j++) {
            float2 v = upk(acc[i][j]);
            int c = 32 * j + 2 * tx;
            orow[c]     = v.x + b0[n0 + c];
            orow[c + 1] = v.y + b0[n0 + c + 1];
        }
    }
}

// ---------------- K3: persistent recurrence, 3 groups, 4x4 thread tiles -------
// Phase p: L0(t=p) and L1(t=p-1). Block owns 8 hidden units (32 gate cols).
// 3 groups x 128 thr, each a full-K GEMM:
//   g0: h0[p-1] x whh0   g1: h0[p-1] x wih1   g2: h1[p-2] x whh1
// Thread tile 4 rows x 4 cols (8 f32x2 accs): per kk = 2 LDS.128 + 8 FFMA2.
// Register-prefetch double buffer; h state K-major in gmem.
#define SMEM_REC 98176
__global__ void __launch_bounds__(384) k_rec(const float* __restrict__ whh0,
                                             const float* __restrict__ wih1,
                                             const float* __restrict__ whh1,
                                             const float* __restrict__ b1) {
    extern __shared__ __align__(16) char smem[];
    float (*SH0)[CH][64]   = (float (*)[CH][64])(smem);               // 16384
    float (*SH1)[CH][64]   = (float (*)[CH][64])(smem + 16384);       // 16384
    float (*SW)[2][CH][36] = (float (*)[2][CH][36])(smem + 32768);    // 27648
    float (*SGD)[64][33]   = (float (*)[64][33])(smem + 60416);       // 25344
    float (*SXW)[32]       = (float (*)[32])(smem + 85760);           // 8192
    float *SC0 = (float*)(smem + 93952);                               // 2048
    float *SC1 = (float*)(smem + 96000);                               // 2048
    float *SB1 = (float*)(smem + 98048);                               // 128

    const int tid = threadIdx.x;
    const int g   = tid >> 7;            // group 0..2
    const int f   = tid & 127;
    const int tx  = f & 7, ty = f >> 3;  // compute: cols 4tx..+3 (32), rows 4ty..+3 (64)
    const int j0  = blockIdx.x * 8;

    // w fill map: kk = f>>2, gate q = f&3 -> cols q*8..q*8+7 (= gmem q*Hh + j0..+7)
    const int kkw = f >> 2, qw = f & 3;
    const float* wsrc = (g == 0) ? whh0 : (g == 1) ? wih1 : whh1;
    // h0 fill (tid<256): 2 float4 each
    const int h0k = tid >> 3, h0p = (tid & 7) * 8;
    // h1 fill (g2): 4 float4 each
    const int h1k = f >> 2, h1p = (f & 3) * 16;

    if (tid < 256) { SC0[tid] = 0.f; SC0[tid + 256] = 0.f; SC1[tid] = 0.f; SC1[tid + 256] = 0.f; }
    if (tid < 32) SB1[tid] = b1[((tid >> 3) << 10) + j0 + (tid & 7)];
    __syncthreads();

    const unsigned sxw_base = smem_u32(&SXW[0][0]);

    float4 ra0, ra1, ra2, ra3, rw0, rw1;

    unsigned tgt = 0;

    for (int p = 0; p < 128; p++) {
        const int cur = p & 1, nxt = cur ^ 1;
        const float* hsrc = (g == 2) ? g_h1[nxt] : g_h0[cur];   // K-major [k][64]

        auto ld_fill = [&](int kb) {
            if (g < 2) {
                const float* s = hsrc + (size_t)(kb + h0k) * 64 + h0p;
                ra0 = __ldcg((const float4*)s);
                ra1 = __ldcg((const float4*)(s + 4));
            } else {
                const float* s = hsrc + (size_t)(kb + h1k) * 64 + h1p;
                ra0 = __ldcg((const float4*)s);
                ra1 = __ldcg((const float4*)(s + 4));
                ra2 = __ldcg((const float4*)(s + 8));
                ra3 = __ldcg((const float4*)(s + 12));
            }
            const float* ws = wsrc + (size_t)(kb + kkw) * G4 + (size_t)qw * Hh + j0;
            rw0 = __ldg((const float4*)ws);
            rw1 = __ldg((const float4*)(ws + 4));
        };
        auto st_fill = [&](int buf) {
            if (g < 2) {
                *(float4*)&SH0[buf][h0k][h0p]     = ra0;
                *(float4*)&SH0[buf][h0k][h0p + 4] = ra1;
            } else {
                *(float4*)&SH1[buf][h1k][h1p]      = ra0;
                *(float4*)&SH1[buf][h1k][h1p + 4]  = ra1;
                *(float4*)&SH1[buf][h1k][h1p + 8]  = ra2;
                *(float4*)&SH1[buf][h1k][h1p + 12] = ra3;
            }
            *(float4*)&SW[g][buf][kkw][qw * 8]     = rw0;
            *(float4*)&SW[g][buf][kkw][qw * 8 + 4] = rw1;
        };
        auto barg = [&]() {
            if (g < 2) asm volatile("bar.sync 1, 256;" ::: "memory");
            else       asm volatile("bar.sync 2, 128;" ::: "memory");
        };

        // xw[t=p] prefetch (64 x 32) via cp.async, tid<256, 2 cp16 each
        if (tid < 256 && p < 127) {
            int b = tid >> 2, q = tid & 3;
            const float* src = g_xw + ((size_t)p * Bz + b) * G4 + (size_t)q * Hh + j0;
            cp16(sxw_base + (unsigned)(b * 32 + q * 8) * 4u, src);
            cp16(sxw_base + (unsigned)(b * 32 + q * 8 + 4) * 4u, src + 4);
            asm volatile("cp.async.commit_group;");
        }

        ull acc[8];
#pragma unroll
        for (int i = 0; i < 8; i++) acc[i] = 0ULL;

        ld_fill(0);
        st_fill(0);
        barg();

        int buf = 0;
        for (int c = 0; c < NCH; c++) {
            if (c < NCH - 1) ld_fill((c + 1) * CH);
            {
                const float* hb = (g < 2) ? &SH0[buf][0][0] : &SH1[buf][0][0];
                const float* wb = &SW[g][buf][0][0];
#pragma unroll
                for (int kk = 0; kk < CH; kk++) {
                    ulonglong2 hA = *(const ulonglong2*)(hb + kk * 64 + 4 * ty);
                    float4 wv     = *(const float4*)(wb + kk * 36 + 4 * tx);
                    ull w0 = pk2(wv.x, wv.x);
                    ull w1 = pk2(wv.y, wv.y);
                    ull w2 = pk2(wv.z, wv.z);
                    ull w3 = pk2(wv.w, wv.w);
                    acc[0] = fma2(hA.x, w0, acc[0]);
                    acc[1] = fma2(hA.y, w0, acc[1]);
                    acc[2] = fma2(hA.x, w1, acc[2]);
                    acc[3] = fma2(hA.y, w1, acc[3]);
                    acc[4] = fma2(hA.x, w2, acc[4]);
                    acc[5] = fma2(hA.y, w2, acc[5]);
                    acc[6] = fma2(hA.x, w3, acc[6]);
                    acc[7] = fma2(hA.y, w3, acc[7]);
                }
            }
            if (c < NCH - 1) st_fill(buf ^ 1);
            barg();
            buf ^= 1;
        }

        // stage gate partials: rows 4ty..+3, cols 4tx..+3
        {
#pragma unroll
            for (int j = 0; j < 4; j++) {
                float2 v = upk(acc[2 * j]);
                float2 u = upk(acc[2 * j + 1]);
                SGD[g][4 * ty + 0][4 * tx + j] = v.x;
                SGD[g][4 * ty + 1][4 * tx + j] = v.y;
                SGD[g][4 * ty + 2][4 * tx + j] = u.x;
                SGD[g][4 * ty + 3][4 * tx + j] = u.y;
            }
        }
        if (tid < 256 && p < 127) asm volatile("cp.async.wait_group 0;");
        __syncthreads();

        if (g == 0) {
            if (p < 127) {
#pragma unroll
                for (int e = 0; e < 4; e++) {
                    int idx = f + 128 * e;             // 0..511
                    int bb = idx & 63, jj = idx >> 6;  // jj 0..7
                    float iv = SGD[0][bb][jj]      + SXW[bb][jj];
                    float fv = SGD[0][bb][8 + jj]  + SXW[bb][8 + jj];
                    float gv = SGD[0][bb][16 + jj] + SXW[bb][16 + jj];
                    float ov = SGD[0][bb][24 + jj] + SXW[bb][24 + jj];
                    float co = SC0[idx];
                    float cn = sigf(fv) * co + sigf(iv) * tanhf(gv);
                    float hn = sigf(ov) * tanhf(cn);
                    SC0[idx] = cn;
                    g_h0[nxt][(size_t)(j0 + jj) * 64 + bb] = hn;
                }
            }
        } else if (g == 1) {
            if (p > 0) {
                int t = p - 1;
#pragma unroll
                for (int e = 0; e < 4; e++) {
                    int idx = f + 128 * e;
                    int bb = idx & 63, jj = idx >> 6;
                    float iv = SGD[1][bb][jj]      + SGD[2][bb][jj]      + SB1[jj];
                    float fv = SGD[1][bb][8 + jj]  + SGD[2][bb][8 + jj]  + SB1[8 + jj];
                    float gv = SGD[1][bb][16 + jj] + SGD[2][bb][16 + jj] + SB1[16 + jj];
                    float ov = SGD[1][bb][24 + jj] + SGD[2][bb][24 + jj] + SB1[24 + jj];
                    float co = SC1[idx];
                    float cn = sigf(fv) * co + sigf(iv) * tanhf(gv);
                    float hn = sigf(ov) * tanhf(cn);
                    SC1[idx] = cn;
                    g_h1[cur][(size_t)(j0 + jj) * 64 + bb] = hn;
                    g_h1all[((size_t)t * Bz + bb) * Hh + j0 + jj] = hn;
                }
            }
        }

        if (p < 127) { tgt += GRID_REC; gbar(tgt); }
    }
}

// ---------------- K4: logits = h1_all @ w_out + b_out (double-buffered) -------
__global__ __launch_bounds__(256, 2) void k_logits(const float* __restrict__ wout,
                                                   const float* __restrict__ bout,
                                                   float* __restrict__ out) {
    __shared__ __align__(16) float As[2][8][132];
    __shared__ __align__(16) ull   Bd[2][8][128];
    __shared__ int aoff[128];

    int tid = threadIdx.x;
    int n0 = blockIdx.x * 128;
    int m0 = blockIdx.y * 128;

    if (tid < 128) {
        int m = m0 + tid;
        int mc = (m < MROWS) ? m : (MROWS - 1);
        int b = mc / 127, t = mc - b * 127;
        aoff[tid] = t * Bz + b;
    }
    __syncthreads();

    int tx = tid & 31, wy = tid >> 5;
    int ar = tid >> 1, akq = tid & 1;
    int bkk = tid >> 5, bc = (tid & 31) * 4;
    bool bok = (n0 + bc + 3 < Vv);

    ull acc[8][4];
#pragma unroll
    for (int p = 0; p < 8; p++)
#pragma unroll
        for (int j = 0; j < 4; j++) acc[p][j] = 0ULL;

    auto ldA = [&](int k0) -> float4 {
        return __ldg((const float4*)(g_h1all + (size_t)aoff[ar] * Hh + k0 + akq * 4));
    };
    auto ldB = [&](int k0) -> float4 {
        float4 bv = make_float4(0.f, 0.f, 0.f, 0.f);
        if (bok) {
            bv = __ldg((const float4*)(wout + (size_t)(k0 + bkk) * Vv + n0 + bc));
        } else {
            const float* wr = wout + (size_t)(k0 + bkk) * Vv;
            if (n0 + bc + 0 < Vv) bv.x = wr[n0 + bc + 0];
            if (n0 + bc + 1 < Vv) bv.y = wr[n0 + bc + 1];
            if (n0 + bc + 2 < Vv) bv.z = wr[n0 + bc + 2];
            if (n0 + bc + 3 < Vv) bv.w = wr[n0 + bc + 3];
        }
        return bv;
    };
    auto sts = [&](int bf, float4 av, float4 bv) {
        As[bf][akq * 4 + 0][ar] = av.x; As[bf][akq * 4 + 1][ar] = av.y;
        As[bf][akq * 4 + 2][ar] = av.z; As[bf][akq * 4 + 3][ar] = av.w;
        Bd[bf][bkk][bc + 0] = pk2(bv.x, bv.x); Bd[bf][bkk][bc + 1] = pk2(bv.y, bv.y);
        Bd[bf][bkk][bc + 2] = pk2(bv.z, bv.z); Bd[bf][bkk][bc + 3] = pk2(bv.w, bv.w);
    };

    float4 av = ldA(0), bv = ldB(0);
    sts(0, av, bv);
    __syncthreads();
    int buf = 0;

    for (int k0 = 0; k0 < Hh; k0 += 8) {
        bool more = (k0 + 8 < Hh);
        if (more) { av = ldA(k0 + 8); bv = ldB(k0 + 8); }
#pragma unroll
        for (int kk = 0; kk < 8; kk++) {
            ulonglong2 A0 = *(const ulonglong2*)&As[buf][kk][wy * 16 + 0];
            ulonglong2 A1 = *(const ulonglong2*)&As[buf][kk][wy * 16 + 4];
            ulonglong2 A2 = *(const ulonglong2*)&As[buf][kk][wy * 16 + 8];
            ulonglong2 A3 = *(const ulonglong2*)&As[buf][kk][wy * 16 + 12];
            ull hr[8] = {A0.x, A0.y, A1.x, A1.y, A2.x, A2.y, A3.x, A3.y};
#pragma unroll
            for (int j = 0; j < 4; j++) {
                ull w = Bd[buf][kk][tx + 32 * j];
#pragma unroll
                for (int p = 0; p < 8; p++) acc[p][j] = fma2(hr[p], w, acc[p][j]);
            }
        }
        if (more) sts(buf ^ 1, av, bv);
        __syncthreads();
        buf ^= 1;
    }

#pragma unroll
    for (int p = 0; p < 8; p++) {
        int m = m0 + wy * 16 + 2 * p;
#pragma unroll
        for (int j = 0; j < 4; j++) {
            int n = n0 + tx + 32 * j;
            if (n < Vv) {
                float2 v = upk(acc[p][j]);
                float bo = bout[n];
                if (m < MROWS)     out[1 + (size_t)m * Vv + n]       = v.x + bo;
                if (m + 1 < MROWS) out[1 + (size_t)(m + 1) * Vv + n] = v.y + bo;
            }
        }
    }
}

// ---------------- K5: per-row log-softmax at gt; masked by PAD ----------------
__global__ __launch_bounds__(256) void k_rowloss(const float* __restrict__ out,
                                                 const int* __restrict__ sent) {
    __shared__ float red[256];
    int m = blockIdx.x;
    const float* row = out + 1 + (size_t)m * Vv;
    int tid = threadIdx.x;

    float mx = -3.4e38f;
    for (int v = tid; v < Vv; v += 256) mx = fmaxf(mx, row[v]);
    red[tid] = mx; __syncthreads();
    for (int s = 128; s > 0; s >>= 1) {
        if (tid < s) red[tid] = fmaxf(red[tid], red[tid + s]);
        __syncthreads();
    }
    mx = red[0]; __syncthreads();

    float sm = 0.f;
    for (int v = tid; v < Vv; v += 256) sm += expf(row[v] - mx);
    red[tid] = sm; __syncthreads();
    for (int s = 128; s > 0; s >>= 1) {
        if (tid < s) red[tid] += red[tid + s];
        __syncthreads();
    }

    if (tid == 0) {
        int b = m / 127, t = m - b * 127;
        int gt = sent[b * Tt + t + 1];
        float lp = 0.f;
        if (gt != 0) lp = row[gt] - mx - logf(red[0]);
        g_rowloss[m] = lp;
    }
}

// ---------------- K6: deterministic loss reduction ----------------
__global__ void k_loss(const int* __restrict__ length, float* __restrict__ out) {
    __shared__ float sb[64];
    int b = threadIdx.x;
    float a = 0.f;
    for (int t = 0; t < TM1; t++) a += g_rowloss[b * TM1 + t];
    sb[b] = -a / (float)length[b];
    __syncthreads();
    if (b == 0) {
        float s = 0.f;
        for (int i = 0; i < 64; i++) s += sb[i];
        out[0] = s;
    }
}

// ---------------- host ----------------
extern "C" void kernel_launch(void* const* d_in, const int* in_sizes, int n_in,
                              void* d_out, int out_size) {
    const int*   sent    = (const int*)d_in[0];
    const int*   length  = (const int*)d_in[1];
    const float* wordvec = (const float*)d_in[2];
    const float* wih0    = (const float*)d_in[3];
    const float* whh0    = (const float*)d_in[4];
    const float* b0      = (const float*)d_in[5];
    const float* wih1    = (const float*)d_in[6];
    const float* whh1    = (const float*)d_in[7];
    const float* b1      = (const float*)d_in[8];
    const float* wout    = (const float*)d_in[9];
    const float* bout    = (const float*)d_in[10];
    float* out = (float*)d_out;

    static int smem_set = 0;
    if (!smem_set) {
        cudaFuncSetAttribute(k_rec, cudaFuncAttributeMaxDynamicSharedMemorySize, SMEM_REC);
        smem_set = 1;
    }

    k_init<<<256, 256>>>();
    k_xw<<<dim3(G4 / 128, 64), 256>>>(sent, wordvec, wih0, b0);
    k_rec<<<GRID_REC, 384, SMEM_REC>>>(whh0, wih1, whh1, b1);
    k_logits<<<dim3((Vv + 127) / 128, (MROWS + 127) / 128), 256>>>(wout, bout, out);
    k_rowloss<<<MROWS, 256>>>(out, sent);
    k_loss<<<1, 64>>>(length, out);
}